// round 10
// baseline (speedup 1.0000x reference)
#include <cuda_runtime.h>
#include <cstdint>

// Problem constants
#define BT    8192
#define KCB   8192
#define DDIM  128
#define TLEN  1024
#define CCH   256
#define NQ    2097152
#define NIDX  16384
#define NCAND 16

// ---------------------------------------------------------------------------
// Scratch (device globals; no allocation allowed)
// ---------------------------------------------------------------------------
__device__ __align__(16) unsigned g_A8[16384 * 32];   // s8 query rows (128B each)
__device__ __align__(16) unsigned g_B8[16384 * 32];   // s8 codeword rows (128B each)
__device__ __align__(16) float2 g_c2sc[16384];        // (c2_k, sc_k)
__device__ float  g_x2[2 * BT];
__device__ float  g_sx[2 * BT];
__device__ float  g_ex2[2 * BT];     // ||x - sx*x8||^2 (exact, fp32)
__device__ float  g_xt2[2 * BT];     // ||sx*x8||^2
__device__ int    g_c2max_bits[2];   // max_k c2 (float bits)
__device__ int    g_ec2max_bits[2];  // max_k ||ec_k||^2 (float bits)
__device__ int    g_candk[2 * BT * NCAND];
__device__ int    g_candn[2 * BT];   // count, or -1 => fallback
__device__ int    g_idx[2 * BT];
__device__ int    g_flagq[2 * BT];
__device__ int    g_nflag;
__device__ double g_sse;

// ---------------------------------------------------------------------------
// PTX helpers (compute_103-legal only: ldmatrix / mma.sync / cp.async)
// ---------------------------------------------------------------------------
__device__ __forceinline__ uint32_t smem_u32(const void* p) {
    uint32_t a;
    asm("{ .reg .u64 t; cvta.to.shared.u64 t, %1; cvt.u32.u64 %0, t; }"
        : "=r"(a) : "l"(p));
    return a;
}
__device__ __forceinline__ void ldsm4(uint32_t& r0, uint32_t& r1,
                                      uint32_t& r2, uint32_t& r3, uint32_t a) {
    asm volatile("ldmatrix.sync.aligned.m8n8.x4.shared.b16 {%0,%1,%2,%3}, [%4];"
                 : "=r"(r0), "=r"(r1), "=r"(r2), "=r"(r3) : "r"(a));
}
__device__ __forceinline__ void mma_s8(int* d, uint32_t a0, uint32_t a1,
                                       uint32_t a2, uint32_t a3,
                                       uint32_t b0, uint32_t b1) {
    asm volatile(
        "mma.sync.aligned.m16n8k32.row.col.s32.s8.s8.s32 "
        "{%0,%1,%2,%3}, {%4,%5,%6,%7}, {%8,%9}, {%0,%1,%2,%3};"
        : "+r"(d[0]), "+r"(d[1]), "+r"(d[2]), "+r"(d[3])
        : "r"(a0), "r"(a1), "r"(a2), "r"(a3), "r"(b0), "r"(b1));
}
__device__ __forceinline__ void cp_async16(uint32_t dst, const void* src) {
    asm volatile("cp.async.cg.shared.global [%0], [%1], 16;"
                 :: "r"(dst), "l"(src) : "memory");
}
#define CP_COMMIT() asm volatile("cp.async.commit_group;" ::: "memory")
#define CP_WAIT0()  asm volatile("cp.async.wait_group 0;" ::: "memory")
#define CP_WAIT1()  asm volatile("cp.async.wait_group 1;" ::: "memory")

__device__ __forceinline__ int clamp127(int v) {
    return v > 127 ? 127 : (v < -127 ? -127 : v);
}
__device__ __forceinline__ unsigned pack_s8x4(int a, int b, int c, int d) {
    return (unsigned)(a & 255) | ((unsigned)(b & 255) << 8) |
           ((unsigned)(c & 255) << 16) | ((unsigned)(d & 255) << 24);
}

// ---------------------------------------------------------------------------
__global__ void init_kernel() {
    if (blockIdx.x == 0 && threadIdx.x == 0) {
        g_sse = 0.0; g_nflag = 0;
        g_c2max_bits[0] = 0; g_c2max_bits[1] = 0;
        g_ec2max_bits[0] = 0; g_ec2max_bits[1] = 0;
    }
}

// splitcb: one warp per codeword row. int8 quantize + (c2, sc) + error maxes.
__global__ void splitcb_kernel(const float* __restrict__ cb) {
    int row  = blockIdx.x * 8 + (threadIdx.x >> 5);
    int lane = threadIdx.x & 31;
    const float4 v = *reinterpret_cast<const float4*>(
        cb + (size_t)row * DDIM + lane * 4);
    float ma = fmaxf(fmaxf(fabsf(v.x), fabsf(v.y)),
                     fmaxf(fabsf(v.z), fabsf(v.w)));
    #pragma unroll
    for (int o = 16; o; o >>= 1)
        ma = fmaxf(ma, __shfl_xor_sync(0xFFFFFFFFu, ma, o));
    float sc  = ma * (1.0f / 127.0f);
    float inv = (ma > 0.f) ? 127.0f / ma : 0.f;
    int q0 = clamp127(__float2int_rn(v.x * inv));
    int q1 = clamp127(__float2int_rn(v.y * inv));
    int q2 = clamp127(__float2int_rn(v.z * inv));
    int q3 = clamp127(__float2int_rn(v.w * inv));
    g_B8[(size_t)row * 32 + lane] = pack_s8x4(q0, q1, q2, q3);
    float e0 = v.x - sc * q0, e1 = v.y - sc * q1;
    float e2 = v.z - sc * q2, e3 = v.w - sc * q3;
    float c2  = v.x * v.x + v.y * v.y + v.z * v.z + v.w * v.w;
    float ec2 = e0 * e0 + e1 * e1 + e2 * e2 + e3 * e3;
    #pragma unroll
    for (int o = 16; o; o >>= 1) {
        c2  += __shfl_down_sync(0xFFFFFFFFu, c2, o);
        ec2 += __shfl_down_sync(0xFFFFFFFFu, ec2, o);
    }
    if (lane == 0) {
        g_c2sc[row] = make_float2(c2, sc);
        atomicMax(&g_c2max_bits[row >> 13], __float_as_int(c2));
        atomicMax(&g_ec2max_bits[row >> 13], __float_as_int(ec2));
    }
}

// split_x: int8 quantize queries + x2 + exact error norms. grid (n,b,tc)=512.
__global__ void split_x_kernel(const float* __restrict__ x) {
    __shared__ float xs[128 * 33];
    int bi = blockIdx.x;
    int n  = bi >> 8;
    int b  = (bi >> 5) & 7;
    int tc = bi & 31;
    int tid = threadIdx.x;
    {   // load 128d x 32t tile, coalesced along t
        int tt = tid & 31, dg = tid >> 5;
        const float* xp = x + ((size_t)b * CCH + (size_t)n * DDIM) * TLEN
                          + tc * 32 + tt;
        #pragma unroll
        for (int j = 0; j < 16; ++j) {
            int d = dg * 16 + j;
            xs[d * 33 + tt] = xp[(size_t)d * TLEN];
        }
    }
    __syncthreads();
    // 8 threads per t-column: sub handles dims sub*16..+15
    int tcol = tid >> 3;
    int sub  = tid & 7;
    float ma = 0.f;
    #pragma unroll
    for (int j = 0; j < 16; ++j)
        ma = fmaxf(ma, fabsf(xs[(sub * 16 + j) * 33 + tcol]));
    #pragma unroll
    for (int o = 4; o; o >>= 1)
        ma = fmaxf(ma, __shfl_xor_sync(0xFFFFFFFFu, ma, o));
    float sx  = ma * (1.0f / 127.0f);
    float inv = (ma > 0.f) ? 127.0f / ma : 0.f;
    int bt = b * TLEN + tc * 32 + tcol;
    float x2 = 0.f, ex2 = 0.f, xt2 = 0.f;
    #pragma unroll
    for (int w = 0; w < 4; ++w) {
        int qv[4];
        #pragma unroll
        for (int c = 0; c < 4; ++c) {
            float xv = xs[(sub * 16 + w * 4 + c) * 33 + tcol];
            int   qi = clamp127(__float2int_rn(xv * inv));
            float xt = sx * qi;
            float e  = xv - xt;
            x2 += xv * xv; ex2 += e * e; xt2 += xt * xt;
            qv[c] = qi;
        }
        g_A8[(size_t)(n * BT + bt) * 32 + sub * 4 + w] =
            pack_s8x4(qv[0], qv[1], qv[2], qv[3]);
    }
    #pragma unroll
    for (int o = 4; o; o >>= 1) {
        x2  += __shfl_xor_sync(0xFFFFFFFFu, x2, o);
        ex2 += __shfl_xor_sync(0xFFFFFFFFu, ex2, o);
        xt2 += __shfl_xor_sync(0xFFFFFFFFu, xt2, o);
    }
    if (sub == 0) {
        int q = n * BT + bt;
        g_x2[q] = x2; g_sx[q] = sx; g_ex2[q] = ex2; g_xt2[q] = xt2;
    }
}

// ---------------------------------------------------------------------------
// vq_mma (int8): one CTA per (cb n, 128-query tile). 512 thr, 16 warps (8m x 2n).
// A 128q x 128B s8 resident; B 64cw x 128B s8 double-buffered. Warp 16q x 32cw.
// 4 k-steps of k32; s32 exact accumulation. Per-thread top-6 per q-row.
// ---------------------------------------------------------------------------
#define ASTRIDE 144
#define BSTRIDE 144
#define SM_A    0
#define SM_B0   18432
#define SM_B1   27648
#define SM_MV   36864          // 128q x 48 floats
#define SM_MK   61440          // 128q x 48 ints
#define SM_TOT  86016

__global__ void __launch_bounds__(512, 1)
vq_mma_kernel() {
    extern __shared__ char smraw[];
    const uint32_t sb = smem_u32(smraw);
    const int tid  = threadIdx.x;
    const int wid  = tid >> 5;
    const int lane = tid & 31;
    const int gq   = lane >> 2;
    const int tq   = lane & 3;
    const int mw   = wid >> 1;          // 0-7 (16q)
    const int nw   = wid & 1;           // 0-1 (32cw)
    const int n    = blockIdx.x >> 6;
    const int qbase = (blockIdx.x & 63) * 128;

    const char* bsrc = (const char*)g_B8 + (size_t)n * KCB * 128;

    // prologue: group0 = A + Btile0 ; group1 = Btile1
    {
        const char* asrc = (const char*)g_A8 + (size_t)(n * BT + qbase) * 128;
        #pragma unroll
        for (int it = 0; it < 2; ++it) {
            int c   = it * 512 + tid;
            int row = c >> 3, col = c & 7;
            cp_async16(sb + SM_A + row * ASTRIDE + col * 16,
                       asrc + (size_t)row * 128 + col * 16);
        }
        {
            int row = tid >> 3, col = tid & 7;
            cp_async16(sb + SM_B0 + row * BSTRIDE + col * 16,
                       bsrc + (size_t)row * 128 + col * 16);
        }
        CP_COMMIT();
        {
            int row = tid >> 3, col = tid & 7;
            cp_async16(sb + SM_B1 + row * BSTRIDE + col * 16,
                       bsrc + (size_t)(64 + row) * 128 + col * 16);
        }
        CP_COMMIT();
    }
    CP_WAIT1();
    __syncthreads();

    const uint32_t lmo = (uint32_t)(lane >> 4) * 16;
    const uint32_t aAddr = sb + SM_A +
        (uint32_t)(mw * 16 + (lane & 15)) * ASTRIDE + lmo;
    const uint32_t bAddrP[2] = {
        sb + SM_B0 + (uint32_t)(nw * 32 + (lane & 15)) * BSTRIDE + lmo,
        sb + SM_B1 + (uint32_t)(nw * 32 + (lane & 15)) * BSTRIDE + lmo };

    // per-thread top-6 lists for 2 q-rows
    float v[2][6];
    int   kk[2][6];
    #pragma unroll
    for (int r = 0; r < 2; ++r)
        #pragma unroll
        for (int j = 0; j < 6; ++j) { v[r][j] = 3.4e38f; kk[r][j] = 0; }

    // scale preload: srow = -2 * sx(q-row)
    float srow[2];
    srow[0] = -2.0f * g_sx[n * BT + qbase + mw * 16 + gq];
    srow[1] = -2.0f * g_sx[n * BT + qbase + mw * 16 + 8 + gq];

    for (int iter = 0; iter < 128; ++iter) {
        int acc[4][4];
        #pragma unroll
        for (int nt = 0; nt < 4; ++nt)
            #pragma unroll
            for (int j = 0; j < 4; ++j) acc[nt][j] = 0;

        const uint32_t bA = bAddrP[iter & 1];
        #pragma unroll
        for (int ks = 0; ks < 4; ++ks) {
            uint32_t a0, a1, a2, a3;
            uint32_t b0x, b0y, b1x, b1y, b0z, b0w, b1z, b1w;
            ldsm4(a0, a1, a2, a3, aAddr + ks * 32);
            ldsm4(b0x, b0y, b1x, b1y, bA + ks * 32);
            ldsm4(b0z, b0w, b1z, b1w, bA + 16 * BSTRIDE + ks * 32);
            mma_s8(acc[0], a0, a1, a2, a3, b0x, b1x);
            mma_s8(acc[1], a0, a1, a2, a3, b0y, b1y);
            mma_s8(acc[2], a0, a1, a2, a3, b0z, b1z);
            mma_s8(acc[3], a0, a1, a2, a3, b0w, b1w);
        }

        // epilogue: s = c2_k + srow*sc_k*D ; per-row top-6 insert
        const int kbw = iter * 64 + nw * 32;
        #pragma unroll
        for (int nt = 0; nt < 4; ++nt) {
            const int kg = kbw + nt * 8 + tq * 2;
            const float4 cs = *reinterpret_cast<const float4*>(
                g_c2sc + n * KCB + kg);            // (c2_0, sc_0, c2_1, sc_1)
            #pragma unroll
            for (int r = 0; r < 2; ++r) {
                float s0 = fmaf(srow[r] * cs.y, (float)acc[nt][r * 2 + 0], cs.x);
                float s1 = fmaf(srow[r] * cs.w, (float)acc[nt][r * 2 + 1], cs.z);
                #pragma unroll
                for (int h = 0; h < 2; ++h) {
                    float s  = h ? s1 : s0;
                    int   ki = kg + h;
                    if (s < v[r][5]) {
                        // insertion sort into 6-slot list
                        int j = 5;
                        #pragma unroll
                        for (int p = 4; p >= 0; --p) {
                            if (s < v[r][p]) {
                                v[r][p + 1] = v[r][p]; kk[r][p + 1] = kk[r][p];
                                j = p;
                            }
                        }
                        v[r][j] = s; kk[r][j] = ki;
                    }
                }
            }
        }

        __syncthreads();
        if (iter + 2 < 128) {
            const char* src = bsrc + (size_t)(iter + 2) * 64 * 128;
            uint32_t dstb = sb + ((iter & 1) ? SM_B1 : SM_B0);
            int row = tid >> 3, col = tid & 7;
            cp_async16(dstb + row * BSTRIDE + col * 16,
                       src + (size_t)row * 128 + col * 16);
            CP_COMMIT();
            CP_WAIT1();
        } else {
            CP_WAIT0();
        }
        __syncthreads();
    }

    // write per-thread top-6 lists: 8 lists x 6 per query
    float* MV = (float*)(smraw + SM_MV);
    int*   MK = (int*)(smraw + SM_MK);
    #pragma unroll
    for (int r = 0; r < 2; ++r) {
        const int ql = mw * 16 + r * 8 + gq;
        const int s0 = ql * 48 + (nw * 4 + tq) * 6;
        #pragma unroll
        for (int j = 0; j < 6; ++j) {
            MV[s0 + j] = v[r][j];
            MK[s0 + j] = kk[r][j];
        }
    }
    __syncthreads();

    // merge + rigorous certificate + candidate emission (thread = query)
    if (tid < 128) {
        const int q = n * BT + qbase + tid;
        float b1 = 3.4e38f;
        int   i1 = 1 << 30;
        #pragma unroll 4
        for (int j = 0; j < 48; ++j) {
            float vv = MV[tid * 48 + j];
            int   kv = MK[tid * 48 + j];
            if (vv < b1 || (vv == b1 && kv < i1)) { b1 = vv; i1 = kv; }
        }
        float minv6 = 3.4e38f;
        #pragma unroll
        for (int l = 0; l < 8; ++l)
            minv6 = fminf(minv6, MV[tid * 48 + l * 6 + 5]);
        // eps = 2*(||ex||*maxc + ||xt||*maxec) + slack ; window = 2*eps
        float cmax  = sqrtf(__int_as_float(g_c2max_bits[n]));
        float ecmax = sqrtf(__int_as_float(g_ec2max_bits[n]));
        float eps = 2.0f * (sqrtf(g_ex2[q]) * cmax + sqrtf(g_xt2[q]) * ecmax)
                    + 5e-3f;
        float win = 2.0f * eps;

        int cnt;
        if (minv6 - b1 <= win) {
            cnt = -1;
        } else {
            cnt = 0;
            float thr = b1 + win;
            #pragma unroll 4
            for (int j = 0; j < 48; ++j) {
                float vv = MV[tid * 48 + j];
                if (vv <= thr) {
                    if (cnt < NCAND) g_candk[q * NCAND + cnt] = MK[tid * 48 + j];
                    ++cnt;
                }
            }
            if (cnt > NCAND) cnt = -1;
        }
        g_candn[q] = cnt;
    }
}

// ---------------------------------------------------------------------------
// exact JAX-order d2 (same structure as all passing rounds)
// ---------------------------------------------------------------------------
__device__ __forceinline__ float exact_d2(const float* __restrict__ x,
                                          const float* __restrict__ cb,
                                          int n, int b, int t, int bt, int k) {
    const float* xp = x + ((size_t)b * CCH + (size_t)n * DDIM) * TLEN + t;
    const float* cp = cb + ((size_t)n * KCB + (size_t)k) * DDIM;
    float xc = 0.f;
    #pragma unroll 8
    for (int d = 0; d < DDIM; ++d) xc = fmaf(xp[(size_t)d * TLEN], cp[d], xc);
    return __fadd_rn(__fsub_rn(g_x2[n * BT + bt], __fmul_rn(2.0f, xc)),
                     g_c2sc[n * KCB + k].x);
}

// ---------------------------------------------------------------------------
// finalize: exact rescore of candidate set; flag fallbacks
// ---------------------------------------------------------------------------
__global__ void finalize_kernel(const float* __restrict__ x,
                                const float* __restrict__ cb,
                                float* __restrict__ out) {
    int q = blockIdx.x * 256 + threadIdx.x;
    int n = q >> 13, bt = q & 8191, b = bt >> 10, t = bt & 1023;
    int cnt = g_candn[q];
    if (cnt < 0) {
        int pos = atomicAdd(&g_nflag, 1);
        g_flagq[pos] = q;
        return;
    }
    int kf;
    if (cnt == 1) {
        kf = g_candk[q * NCAND];
    } else {
        float bd = 3.4e38f;
        kf = 1 << 30;
        for (int i = 0; i < cnt; ++i) {
            int   k = g_candk[q * NCAND + i];
            float d = exact_d2(x, cb, n, b, t, bt, k);
            if (d < bd || (d == bd && k < kf)) { bd = d; kf = k; }
        }
    }
    g_idx[q] = kf;
    out[NQ + ((size_t)b * 2 + n) * TLEN + t] = (float)kf;
}

// ---------------------------------------------------------------------------
// fallback: exact full scan for flagged queries (expected ~0-20)
// ---------------------------------------------------------------------------
__global__ void fallback_kernel(const float* __restrict__ x,
                                const float* __restrict__ cb,
                                float* __restrict__ out) {
    __shared__ float sv[256];
    __shared__ int   sk[256];
    int nf = g_nflag;
    for (int i = blockIdx.x; i < nf; i += 128) {
        int q = g_flagq[i];
        int n = q >> 13, bt = q & 8191, b = bt >> 10, t = bt & 1023;
        float bv = 3.4e38f;
        int   bk = 1 << 30;
        for (int j = 0; j < 32; ++j) {
            int k = threadIdx.x + j * 256;
            float d2 = exact_d2(x, cb, n, b, t, bt, k);
            if (d2 < bv || (d2 == bv && k < bk)) { bv = d2; bk = k; }
        }
        sv[threadIdx.x] = bv;
        sk[threadIdx.x] = bk;
        __syncthreads();
        for (int o = 128; o; o >>= 1) {
            if (threadIdx.x < o) {
                float ov = sv[threadIdx.x + o];
                int   ok = sk[threadIdx.x + o];
                if (ov < sv[threadIdx.x] ||
                    (ov == sv[threadIdx.x] && ok < sk[threadIdx.x])) {
                    sv[threadIdx.x] = ov; sk[threadIdx.x] = ok;
                }
            }
            __syncthreads();
        }
        if (threadIdx.x == 0) {
            g_idx[q] = sk[0];
            out[NQ + ((size_t)b * 2 + n) * TLEN + t] = (float)sk[0];
        }
        __syncthreads();
    }
}

// ---------------------------------------------------------------------------
// gather: coalesced quantized-output writes + commit-loss SSE.
// grid (n:2, b:8, tc:32) = 512 blocks, 256 threads. smem-transposed tile.
// ---------------------------------------------------------------------------
__global__ void gather_kernel(const float* __restrict__ x,
                              const float* __restrict__ cb,
                              float* __restrict__ out) {
    __shared__ float qs[128 * 33];
    __shared__ int   kq[32];
    __shared__ float red[8];
    int bi = blockIdx.x;
    int n  = bi >> 8;
    int b  = (bi >> 5) & 7;
    int tc = bi & 31;
    int tid = threadIdx.x;
    if (tid < 32) kq[tid] = g_idx[n * BT + b * TLEN + tc * 32 + tid];
    __syncthreads();
    // gather 32 codeword rows (coalesced 512B reads), transpose into smem
    #pragma unroll
    for (int j = 0; j < 16; ++j) {
        int idx = j * 256 + tid;
        int cw  = idx >> 7;
        int d   = idx & 127;
        qs[d * 33 + cw] = cb[((size_t)n * KCB + kq[cw]) * DDIM + d];
    }
    __syncthreads();
    // coalesced writes along t + SSE
    float acc = 0.f;
    #pragma unroll
    for (int j = 0; j < 16; ++j) {
        int idx = j * 256 + tid;
        int d   = idx >> 5;
        int tt  = idx & 31;
        float w = qs[d * 33 + tt];
        size_t addr = ((size_t)b * CCH + (size_t)n * DDIM + d) * TLEN
                      + tc * 32 + tt;
        out[addr] = w;
        float df = x[addr] - w;
        acc += df * df;
    }
    #pragma unroll
    for (int o = 16; o; o >>= 1) acc += __shfl_down_sync(0xFFFFFFFFu, acc, o);
    if ((tid & 31) == 0) red[tid >> 5] = acc;
    __syncthreads();
    if (tid == 0) {
        float tot = 0.f;
        #pragma unroll
        for (int j = 0; j < 8; ++j) tot += red[j];
        atomicAdd(&g_sse, (double)tot);
    }
}

__global__ void fin_kernel(float* __restrict__ out) {
    out[NQ + NIDX] = (float)(0.25 * g_sse / (double)((long long)BT * DDIM));
}

// ---------------------------------------------------------------------------
extern "C" void kernel_launch(void* const* d_in, const int* in_sizes, int n_in,
                              void* d_out, int out_size) {
    const float* x  = (const float*)d_in[0];
    const float* cb = (const float*)d_in[1];
    float* out = (float*)d_out;

    cudaFuncSetAttribute(vq_mma_kernel,
                         cudaFuncAttributeMaxDynamicSharedMemorySize, SM_TOT);

    init_kernel<<<1, 32>>>();
    splitcb_kernel<<<2048, 256>>>(cb);
    split_x_kernel<<<512, 256>>>(x);
    vq_mma_kernel<<<128, 512, SM_TOT>>>();
    finalize_kernel<<<64, 256>>>(x, cb, out);
    fallback_kernel<<<128, 256>>>(x, cb, out);
    gather_kernel<<<512, 256>>>(x, cb, out);
    fin_kernel<<<1, 1>>>(out);
}

// round 11
// speedup vs baseline: 4.7185x; 4.7185x over previous
#include <cuda_runtime.h>
#include <cuda_fp16.h>
#include <cstdint>

// Problem constants
#define BT    8192
#define KCB   8192
#define DDIM  128
#define TLEN  1024
#define CCH   256
#define NQ    2097152
#define NIDX  16384
#define NCAND 8

// ---------------------------------------------------------------------------
// Scratch (device globals; no allocation allowed)
// ---------------------------------------------------------------------------
__device__ __align__(16) unsigned g_Ahat[16384 * 64];  // f16x2 xh row (256B each)
__device__ __align__(16) unsigned g_Bhat[16384 * 64];  // f16x2 ch row (256B each)
__device__ float  g_c2[2 * KCB];
__device__ float  g_x2[2 * BT];
__device__ float  g_ex2[2 * BT];     // ||x - xh||^2  (exact)
__device__ float  g_xh2[2 * BT];     // ||xh||^2      (exact)
__device__ int    g_c2max_bits[2];   // max_k ||c_k||^2   (float bits)
__device__ int    g_ec2max_bits[2];  // max_k ||c-ch||^2  (float bits)
__device__ int    g_candk[2 * BT * NCAND];
__device__ int    g_candn[2 * BT];   // count, or -1 => fallback
__device__ int    g_idx[2 * BT];
__device__ int    g_flagq[2 * BT];
__device__ int    g_nflag;
__device__ double g_sse;

// ---------------------------------------------------------------------------
// PTX helpers (compute_103-legal only: ldmatrix / mma.sync / cp.async)
// ---------------------------------------------------------------------------
__device__ __forceinline__ uint32_t smem_u32(const void* p) {
    uint32_t a;
    asm("{ .reg .u64 t; cvta.to.shared.u64 t, %1; cvt.u32.u64 %0, t; }"
        : "=r"(a) : "l"(p));
    return a;
}
__device__ __forceinline__ void ldsm4(uint32_t& r0, uint32_t& r1,
                                      uint32_t& r2, uint32_t& r3, uint32_t a) {
    asm volatile("ldmatrix.sync.aligned.m8n8.x4.shared.b16 {%0,%1,%2,%3}, [%4];"
                 : "=r"(r0), "=r"(r1), "=r"(r2), "=r"(r3) : "r"(a));
}
__device__ __forceinline__ void mma_f16(float* d, uint32_t a0, uint32_t a1,
                                        uint32_t a2, uint32_t a3,
                                        uint32_t b0, uint32_t b1) {
    asm volatile(
        "mma.sync.aligned.m16n8k16.row.col.f32.f16.f16.f32 "
        "{%0,%1,%2,%3}, {%4,%5,%6,%7}, {%8,%9}, {%0,%1,%2,%3};"
        : "+f"(d[0]), "+f"(d[1]), "+f"(d[2]), "+f"(d[3])
        : "r"(a0), "r"(a1), "r"(a2), "r"(a3), "r"(b0), "r"(b1));
}
__device__ __forceinline__ void cp_async16(uint32_t dst, const void* src) {
    asm volatile("cp.async.cg.shared.global [%0], [%1], 16;"
                 :: "r"(dst), "l"(src) : "memory");
}
#define CP_COMMIT() asm volatile("cp.async.commit_group;" ::: "memory")
#define CP_WAIT0()  asm volatile("cp.async.wait_group 0;" ::: "memory")
#define CP_WAIT1()  asm volatile("cp.async.wait_group 1;" ::: "memory")

__device__ __forceinline__ unsigned pack_h2(__half a, __half b) {
    unsigned short ua = __half_as_ushort(a), ub = __half_as_ushort(b);
    return (unsigned)ua | ((unsigned)ub << 16);
}

// ---------------------------------------------------------------------------
__global__ void init_kernel() {
    if (blockIdx.x == 0 && threadIdx.x == 0) {
        g_sse = 0.0; g_nflag = 0;
        g_c2max_bits[0] = 0; g_c2max_bits[1] = 0;
        g_ec2max_bits[0] = 0; g_ec2max_bits[1] = 0;
    }
}

// splitcb: one warp per codeword row -> Bhat(f16 ch), c2, max c2, max ||ec||^2
__global__ void splitcb_kernel(const float* __restrict__ cb) {
    int row  = blockIdx.x * 8 + (threadIdx.x >> 5);
    int lane = threadIdx.x & 31;
    const float4 v = *reinterpret_cast<const float4*>(
        cb + (size_t)row * DDIM + lane * 4);
    __half h0 = __float2half_rn(v.x), h1 = __float2half_rn(v.y);
    __half h2 = __float2half_rn(v.z), h3 = __float2half_rn(v.w);
    g_Bhat[(size_t)row * 64 + 2 * lane]     = pack_h2(h0, h1);
    g_Bhat[(size_t)row * 64 + 2 * lane + 1] = pack_h2(h2, h3);
    float e0 = v.x - __half2float(h0), e1 = v.y - __half2float(h1);
    float e2 = v.z - __half2float(h2), e3 = v.w - __half2float(h3);
    float c2  = v.x * v.x + v.y * v.y + v.z * v.z + v.w * v.w;
    float ec2 = e0 * e0 + e1 * e1 + e2 * e2 + e3 * e3;
    #pragma unroll
    for (int o = 16; o; o >>= 1) {
        c2  += __shfl_down_sync(0xFFFFFFFFu, c2, o);
        ec2 += __shfl_down_sync(0xFFFFFFFFu, ec2, o);
    }
    if (lane == 0) {
        g_c2[row] = c2;
        atomicMax(&g_c2max_bits[row >> 13], __float_as_int(c2));
        atomicMax(&g_ec2max_bits[row >> 13], __float_as_int(ec2));
    }
}

// split_x: f16 quantize queries + x2 + exact error norms. grid (n,b,tc)=512.
__global__ void split_x_kernel(const float* __restrict__ x) {
    __shared__ float xs[128 * 33];
    int bi = blockIdx.x;
    int n  = bi >> 8;
    int b  = (bi >> 5) & 7;
    int tc = bi & 31;
    int tid = threadIdx.x;
    {   // load 128d x 32t tile, coalesced along t
        int tt = tid & 31, dg = tid >> 5;
        const float* xp = x + ((size_t)b * CCH + (size_t)n * DDIM) * TLEN
                          + tc * 32 + tt;
        #pragma unroll
        for (int j = 0; j < 16; ++j) {
            int d = dg * 16 + j;
            xs[d * 33 + tt] = xp[(size_t)d * TLEN];
        }
    }
    __syncthreads();
    // 8 threads per t-column: sub handles dims sub*16..+15 (8 u32 words)
    int tcol = tid >> 3;
    int sub  = tid & 7;
    int bt   = b * TLEN + tc * 32 + tcol;
    float x2 = 0.f, ex2 = 0.f, xh2 = 0.f;
    #pragma unroll
    for (int w = 0; w < 8; ++w) {
        float a  = xs[(sub * 16 + 2 * w) * 33 + tcol];
        float bb = xs[(sub * 16 + 2 * w + 1) * 33 + tcol];
        __half ha = __float2half_rn(a), hb = __float2half_rn(bb);
        float fa = __half2float(ha), fb = __half2float(hb);
        float ea = a - fa, eb = bb - fb;
        x2  += a * a + bb * bb;
        ex2 += ea * ea + eb * eb;
        xh2 += fa * fa + fb * fb;
        g_Ahat[(size_t)(n * BT + bt) * 64 + sub * 8 + w] = pack_h2(ha, hb);
    }
    #pragma unroll
    for (int o = 4; o; o >>= 1) {
        x2  += __shfl_xor_sync(0xFFFFFFFFu, x2, o);
        ex2 += __shfl_xor_sync(0xFFFFFFFFu, ex2, o);
        xh2 += __shfl_xor_sync(0xFFFFFFFFu, xh2, o);
    }
    if (sub == 0) {
        int q = n * BT + bt;
        g_x2[q] = x2; g_ex2[q] = ex2; g_xh2[q] = xh2;
    }
}

// ---------------------------------------------------------------------------
// vq_mma (single-term f16): one CTA per (cb n, 128-query tile).
// 512 thr, 16 warps (8m x 2n). A 128q x 128 f16 resident; B 64cw x 128 f16
// double-buffered via cp.async (true overlap). Warp tile 16q x 32cw; K=128.
// Per-thread top-3 per q-row; per-thread-v3 certificate; candidate emission.
// ---------------------------------------------------------------------------
#define ASTRIDE 272
#define BSTRIDE 272
#define SM_A    0
#define SM_B0   34816
#define SM_B1   52224
#define SM_MV   69632          // 128q x 24 floats
#define SM_MK   81920          // 128q x 24 ints
#define SM_TOT  94208

__global__ void __launch_bounds__(512, 1)
vq_mma_kernel() {
    extern __shared__ char smraw[];
    const uint32_t sb = smem_u32(smraw);
    const int tid  = threadIdx.x;
    const int wid  = tid >> 5;
    const int lane = tid & 31;
    const int gq   = lane >> 2;
    const int tq   = lane & 3;
    const int mw   = wid >> 1;          // 0-7 (16q each)
    const int nw   = wid & 1;           // 0-1 (32cw each)
    const int n    = blockIdx.x >> 6;
    const int qbase = (blockIdx.x & 63) * 128;

    const char* bsrc = (const char*)g_Bhat + (size_t)n * KCB * 256;

    // prologue: group0 = A + Btile0 ; group1 = Btile1
    {
        const char* asrc = (const char*)g_Ahat + (size_t)(n * BT + qbase) * 256;
        #pragma unroll
        for (int it = 0; it < 4; ++it) {
            int c   = it * 512 + tid;
            int row = c >> 4, col = c & 15;
            cp_async16(sb + SM_A + row * ASTRIDE + col * 16,
                       asrc + (size_t)row * 256 + col * 16);
        }
        #pragma unroll
        for (int it = 0; it < 2; ++it) {
            int c   = it * 512 + tid;
            int row = c >> 4, col = c & 15;
            cp_async16(sb + SM_B0 + row * BSTRIDE + col * 16,
                       bsrc + (size_t)row * 256 + col * 16);
        }
        CP_COMMIT();
        #pragma unroll
        for (int it = 0; it < 2; ++it) {
            int c   = it * 512 + tid;
            int row = c >> 4, col = c & 15;
            cp_async16(sb + SM_B1 + row * BSTRIDE + col * 16,
                       bsrc + (size_t)(64 + row) * 256 + col * 16);
        }
        CP_COMMIT();
    }
    CP_WAIT1();
    __syncthreads();

    const uint32_t lmo = (uint32_t)(lane >> 4) * 16;
    const uint32_t aAddr = sb + SM_A +
        (uint32_t)(mw * 16 + (lane & 15)) * ASTRIDE + lmo;
    const uint32_t bAddrP[2] = {
        sb + SM_B0 + (uint32_t)(nw * 32 + (lane & 15)) * BSTRIDE + lmo,
        sb + SM_B1 + (uint32_t)(nw * 32 + (lane & 15)) * BSTRIDE + lmo };

    float v1[2], v2[2], v3[2];
    int   k1[2], k2[2];
    #pragma unroll
    for (int i = 0; i < 2; ++i) {
        v1[i] = v2[i] = v3[i] = 3.4e38f;
        k1[i] = k2[i] = 0;
    }

    for (int iter = 0; iter < 128; ++iter) {
        float acc[4][4];
        #pragma unroll
        for (int nt = 0; nt < 4; ++nt)
            #pragma unroll
            for (int j = 0; j < 4; ++j) acc[nt][j] = 0.f;

        const uint32_t bA = bAddrP[iter & 1];
        #pragma unroll
        for (int ks = 0; ks < 8; ++ks) {
            uint32_t a0, a1, a2, a3;
            uint32_t b0x, b0y, b1x, b1y, b0z, b0w, b1z, b1w;
            ldsm4(a0, a1, a2, a3, aAddr + ks * 32);
            ldsm4(b0x, b0y, b1x, b1y, bA + ks * 32);
            ldsm4(b0z, b0w, b1z, b1w, bA + 16 * BSTRIDE + ks * 32);
            mma_f16(acc[0], a0, a1, a2, a3, b0x, b1x);
            mma_f16(acc[1], a0, a1, a2, a3, b0y, b1y);
            mma_f16(acc[2], a0, a1, a2, a3, b0z, b1z);
            mma_f16(acc[3], a0, a1, a2, a3, b0w, b1w);
        }

        // epilogue: s = c2[k] - 2*xc, per-row top-3
        const int kbw = iter * 64 + nw * 32;
        #pragma unroll
        for (int nt = 0; nt < 4; ++nt) {
            const int kg = kbw + nt * 8 + tq * 2;
            const float2 c2p = __ldg(reinterpret_cast<const float2*>(
                g_c2 + n * KCB + kg));
            #pragma unroll
            for (int r = 0; r < 2; ++r) {
                float s0 = fmaf(acc[nt][r * 2 + 0], -2.0f, c2p.x);
                float s1 = fmaf(acc[nt][r * 2 + 1], -2.0f, c2p.y);
                if (s0 < v3[r]) {
                    if (s0 < v2[r]) {
                        v3[r] = v2[r];
                        if (s0 < v1[r]) { v2[r] = v1[r]; k2[r] = k1[r];
                                          v1[r] = s0;    k1[r] = kg; }
                        else            { v2[r] = s0;    k2[r] = kg; }
                    } else v3[r] = s0;
                }
                if (s1 < v3[r]) {
                    if (s1 < v2[r]) {
                        v3[r] = v2[r];
                        if (s1 < v1[r]) { v2[r] = v1[r]; k2[r] = k1[r];
                                          v1[r] = s1;    k1[r] = kg + 1; }
                        else            { v2[r] = s1;    k2[r] = kg + 1; }
                    } else v3[r] = s1;
                }
            }
        }

        __syncthreads();
        if (iter + 2 < 128) {
            const char* src = bsrc + (size_t)(iter + 2) * 64 * 256;
            uint32_t dstb = sb + ((iter & 1) ? SM_B1 : SM_B0);
            #pragma unroll
            for (int it = 0; it < 2; ++it) {
                int c   = it * 512 + tid;
                int row = c >> 4, col = c & 15;
                cp_async16(dstb + row * BSTRIDE + col * 16,
                           src + (size_t)row * 256 + col * 16);
            }
            CP_COMMIT();
            CP_WAIT1();
        } else {
            CP_WAIT0();
        }
        __syncthreads();
    }

    // write per-thread top-3 lists (8 lists x 3 per query)
    float* MV = (float*)(smraw + SM_MV);
    int*   MK = (int*)(smraw + SM_MK);
    #pragma unroll
    for (int r = 0; r < 2; ++r) {
        const int ql = mw * 16 + r * 8 + gq;
        const int s0 = ql * 24 + (nw * 4 + tq) * 3;
        MV[s0 + 0] = v1[r]; MK[s0 + 0] = k1[r];
        MV[s0 + 1] = v2[r]; MK[s0 + 1] = k2[r];
        MV[s0 + 2] = v3[r]; MK[s0 + 2] = 0;
    }
    __syncthreads();

    // merge + computed rigorous window + candidate emission (thread = query)
    if (tid < 128) {
        const int q = n * BT + qbase + tid;
        float b1 = 3.4e38f;
        int   i1 = 1 << 30;
        #pragma unroll 4
        for (int j = 0; j < 24; ++j) {
            float vv = MV[tid * 24 + j];
            int   kv = MK[tid * 24 + j];
            if (vv < b1 || (vv == b1 && kv < i1)) { b1 = vv; i1 = kv; }
        }
        float minv3 = 3.4e38f;
        #pragma unroll
        for (int l = 0; l < 8; ++l)
            minv3 = fminf(minv3, MV[tid * 24 + l * 3 + 2]);
        // win = 2*eps_q; eps_q = 2*(||ex||*maxc + ||xh||*maxec) + accum slack
        float cmax  = sqrtf(__int_as_float(g_c2max_bits[n]));
        float ecmax = sqrtf(__int_as_float(g_ec2max_bits[n]));
        float win = 4.0f * (sqrtf(g_ex2[q]) * cmax + sqrtf(g_xh2[q]) * ecmax)
                    + 2e-3f;

        int cnt;
        if (minv3 - b1 <= win) {
            cnt = -1;
        } else {
            cnt = 0;
            float thr = b1 + win;
            #pragma unroll 4
            for (int j = 0; j < 24; ++j) {
                float vv = MV[tid * 24 + j];
                if (vv <= thr) {
                    if (cnt < NCAND) g_candk[q * NCAND + cnt] = MK[tid * 24 + j];
                    ++cnt;
                }
            }
            if (cnt > NCAND) cnt = -1;
        }
        g_candn[q] = cnt;
    }
}

// ---------------------------------------------------------------------------
// exact JAX-order d2 (same arithmetic as all passing rounds)
// ---------------------------------------------------------------------------
__device__ __forceinline__ float exact_d2(const float* __restrict__ x,
                                          const float* __restrict__ cb,
                                          int n, int b, int t, int bt, int k) {
    const float* xp = x + ((size_t)b * CCH + (size_t)n * DDIM) * TLEN + t;
    const float* cp = cb + ((size_t)n * KCB + (size_t)k) * DDIM;
    float xc = 0.f;
    #pragma unroll 8
    for (int d = 0; d < DDIM; ++d) xc = fmaf(xp[(size_t)d * TLEN], cp[d], xc);
    return __fadd_rn(__fsub_rn(g_x2[n * BT + bt], __fmul_rn(2.0f, xc)),
                     g_c2[n * KCB + k]);
}

// ---------------------------------------------------------------------------
// finalize: exact rescore of the candidate set; flag fallbacks
// ---------------------------------------------------------------------------
__global__ void finalize_kernel(const float* __restrict__ x,
                                const float* __restrict__ cb,
                                float* __restrict__ out) {
    int q = blockIdx.x * 256 + threadIdx.x;
    int n = q >> 13, bt = q & 8191, b = bt >> 10, t = bt & 1023;
    int cnt = g_candn[q];
    if (cnt < 0) {
        int pos = atomicAdd(&g_nflag, 1);
        g_flagq[pos] = q;
        return;
    }
    int kf;
    if (cnt == 1) {
        kf = g_candk[q * NCAND];
    } else {
        float bd = 3.4e38f;
        kf = 1 << 30;
        for (int i = 0; i < cnt; ++i) {
            int   k = g_candk[q * NCAND + i];
            float d = exact_d2(x, cb, n, b, t, bt, k);
            if (d < bd || (d == bd && k < kf)) { bd = d; kf = k; }
        }
    }
    g_idx[q] = kf;
    out[NQ + ((size_t)b * 2 + n) * TLEN + t] = (float)kf;
}

// ---------------------------------------------------------------------------
// fallback: exact full scan for flagged queries (expected ~0-30)
// ---------------------------------------------------------------------------
__global__ void fallback_kernel(const float* __restrict__ x,
                                const float* __restrict__ cb,
                                float* __restrict__ out) {
    __shared__ float sv[256];
    __shared__ int   sk[256];
    int nf = g_nflag;
    for (int i = blockIdx.x; i < nf; i += 128) {
        int q = g_flagq[i];
        int n = q >> 13, bt = q & 8191, b = bt >> 10, t = bt & 1023;
        float bv = 3.4e38f;
        int   bk = 1 << 30;
        for (int j = 0; j < 32; ++j) {
            int k = threadIdx.x + j * 256;
            float d2 = exact_d2(x, cb, n, b, t, bt, k);
            if (d2 < bv || (d2 == bv && k < bk)) { bv = d2; bk = k; }
        }
        sv[threadIdx.x] = bv;
        sk[threadIdx.x] = bk;
        __syncthreads();
        for (int o = 128; o; o >>= 1) {
            if (threadIdx.x < o) {
                float ov = sv[threadIdx.x + o];
                int   ok = sk[threadIdx.x + o];
                if (ov < sv[threadIdx.x] ||
                    (ov == sv[threadIdx.x] && ok < sk[threadIdx.x])) {
                    sv[threadIdx.x] = ov; sk[threadIdx.x] = ok;
                }
            }
            __syncthreads();
        }
        if (threadIdx.x == 0) {
            g_idx[q] = sk[0];
            out[NQ + ((size_t)b * 2 + n) * TLEN + t] = (float)sk[0];
        }
        __syncthreads();
    }
}

// ---------------------------------------------------------------------------
// gather: coalesced quantized-output writes + commit-loss SSE.
// grid (n:2, b:8, tc:32) = 512 blocks, 256 threads. smem-transposed tile.
// ---------------------------------------------------------------------------
__global__ void gather_kernel(const float* __restrict__ x,
                              const float* __restrict__ cb,
                              float* __restrict__ out) {
    __shared__ float qs[128 * 33];
    __shared__ int   kq[32];
    __shared__ float red[8];
    int bi = blockIdx.x;
    int n  = bi >> 8;
    int b  = (bi >> 5) & 7;
    int tc = bi & 31;
    int tid = threadIdx.x;
    if (tid < 32) kq[tid] = g_idx[n * BT + b * TLEN + tc * 32 + tid];
    __syncthreads();
    #pragma unroll
    for (int j = 0; j < 16; ++j) {
        int idx = j * 256 + tid;
        int cw  = idx >> 7;
        int d   = idx & 127;
        qs[d * 33 + cw] = cb[((size_t)n * KCB + kq[cw]) * DDIM + d];
    }
    __syncthreads();
    float acc = 0.f;
    #pragma unroll
    for (int j = 0; j < 16; ++j) {
        int idx = j * 256 + tid;
        int d   = idx >> 5;
        int tt  = idx & 31;
        float w = qs[d * 33 + tt];
        size_t addr = ((size_t)b * CCH + (size_t)n * DDIM + d) * TLEN
                      + tc * 32 + tt;
        out[addr] = w;
        float df = x[addr] - w;
        acc += df * df;
    }
    #pragma unroll
    for (int o = 16; o; o >>= 1) acc += __shfl_down_sync(0xFFFFFFFFu, acc, o);
    if ((tid & 31) == 0) red[tid >> 5] = acc;
    __syncthreads();
    if (tid == 0) {
        float tot = 0.f;
        #pragma unroll
        for (int j = 0; j < 8; ++j) tot += red[j];
        atomicAdd(&g_sse, (double)tot);
    }
}

__global__ void fin_kernel(float* __restrict__ out) {
    out[NQ + NIDX] = (float)(0.25 * g_sse / (double)((long long)BT * DDIM));
}

// ---------------------------------------------------------------------------
extern "C" void kernel_launch(void* const* d_in, const int* in_sizes, int n_in,
                              void* d_out, int out_size) {
    const float* x  = (const float*)d_in[0];
    const float* cb = (const float*)d_in[1];
    float* out = (float*)d_out;

    cudaFuncSetAttribute(vq_mma_kernel,
                         cudaFuncAttributeMaxDynamicSharedMemorySize, SM_TOT);

    init_kernel<<<1, 32>>>();
    splitcb_kernel<<<2048, 256>>>(cb);
    split_x_kernel<<<512, 256>>>(x);
    vq_mma_kernel<<<128, 512, SM_TOT>>>();
    finalize_kernel<<<64, 256>>>(x, cb, out);
    fallback_kernel<<<128, 256>>>(x, cb, out);
    gather_kernel<<<512, 256>>>(x, cb, out);
    fin_kernel<<<1, 1>>>(out);
}

// round 12
// speedup vs baseline: 5.4804x; 1.1615x over previous
#include <cuda_runtime.h>
#include <cuda_fp16.h>
#include <cstdint>

// Problem constants
#define BT    8192
#define KCB   8192
#define DDIM  128
#define TLEN  1024
#define CCH   256
#define NQ    2097152
#define NIDX  16384
#define NCAND 16

// ---------------------------------------------------------------------------
// Scratch (device globals; no allocation allowed)
// ---------------------------------------------------------------------------
__device__ __align__(16) unsigned g_Ahat[16384 * 64];  // f16x2 xh row (256B each)
__device__ __align__(16) unsigned g_Bhat[16384 * 64];  // f16x2 ch row (256B each)
__device__ float  g_c2[2 * KCB];
__device__ float  g_x2[2 * BT];
__device__ float  g_ex2[2 * BT];     // ||x - xh||^2  (exact)
__device__ float  g_xh2[2 * BT];     // ||xh||^2      (exact)
__device__ int    g_c2max_bits[2];   // max_k ||c_k||^2   (float bits)
__device__ int    g_ec2max_bits[2];  // max_k ||c-ch||^2  (float bits)
__device__ int    g_candk[2 * BT * NCAND];
__device__ int    g_candn[2 * BT];   // count, or -1 => fallback
__device__ int    g_idx[2 * BT];
__device__ int    g_flagq[2 * BT];
__device__ int    g_nflag;
__device__ double g_sse;

// ---------------------------------------------------------------------------
// PTX helpers (compute_103-legal only: ldmatrix / mma.sync / cp.async)
// ---------------------------------------------------------------------------
__device__ __forceinline__ uint32_t smem_u32(const void* p) {
    uint32_t a;
    asm("{ .reg .u64 t; cvta.to.shared.u64 t, %1; cvt.u32.u64 %0, t; }"
        : "=r"(a) : "l"(p));
    return a;
}
__device__ __forceinline__ void ldsm4(uint32_t& r0, uint32_t& r1,
                                      uint32_t& r2, uint32_t& r3, uint32_t a) {
    asm volatile("ldmatrix.sync.aligned.m8n8.x4.shared.b16 {%0,%1,%2,%3}, [%4];"
                 : "=r"(r0), "=r"(r1), "=r"(r2), "=r"(r3) : "r"(a));
}
__device__ __forceinline__ void mma_f16(float* d, uint32_t a0, uint32_t a1,
                                        uint32_t a2, uint32_t a3,
                                        uint32_t b0, uint32_t b1) {
    asm volatile(
        "mma.sync.aligned.m16n8k16.row.col.f32.f16.f16.f32 "
        "{%0,%1,%2,%3}, {%4,%5,%6,%7}, {%8,%9}, {%0,%1,%2,%3};"
        : "+f"(d[0]), "+f"(d[1]), "+f"(d[2]), "+f"(d[3])
        : "r"(a0), "r"(a1), "r"(a2), "r"(a3), "r"(b0), "r"(b1));
}
__device__ __forceinline__ void cp_async16(uint32_t dst, const void* src) {
    asm volatile("cp.async.cg.shared.global [%0], [%1], 16;"
                 :: "r"(dst), "l"(src) : "memory");
}
#define CP_COMMIT() asm volatile("cp.async.commit_group;" ::: "memory")
#define CP_WAIT0()  asm volatile("cp.async.wait_group 0;" ::: "memory")
#define CP_WAIT1()  asm volatile("cp.async.wait_group 1;" ::: "memory")

__device__ __forceinline__ unsigned pack_h2(__half a, __half b) {
    unsigned short ua = __half_as_ushort(a), ub = __half_as_ushort(b);
    return (unsigned)ua | ((unsigned)ub << 16);
}

// ---------------------------------------------------------------------------
__global__ void init_kernel() {
    if (blockIdx.x == 0 && threadIdx.x == 0) {
        g_sse = 0.0; g_nflag = 0;
        g_c2max_bits[0] = 0; g_c2max_bits[1] = 0;
        g_ec2max_bits[0] = 0; g_ec2max_bits[1] = 0;
    }
}

// splitcb: one warp per codeword row -> Bhat(f16 ch), c2, max c2, max ||ec||^2
__global__ void splitcb_kernel(const float* __restrict__ cb) {
    int row  = blockIdx.x * 8 + (threadIdx.x >> 5);
    int lane = threadIdx.x & 31;
    const float4 v = *reinterpret_cast<const float4*>(
        cb + (size_t)row * DDIM + lane * 4);
    __half h0 = __float2half_rn(v.x), h1 = __float2half_rn(v.y);
    __half h2 = __float2half_rn(v.z), h3 = __float2half_rn(v.w);
    g_Bhat[(size_t)row * 64 + 2 * lane]     = pack_h2(h0, h1);
    g_Bhat[(size_t)row * 64 + 2 * lane + 1] = pack_h2(h2, h3);
    float e0 = v.x - __half2float(h0), e1 = v.y - __half2float(h1);
    float e2 = v.z - __half2float(h2), e3 = v.w - __half2float(h3);
    float c2  = v.x * v.x + v.y * v.y + v.z * v.z + v.w * v.w;
    float ec2 = e0 * e0 + e1 * e1 + e2 * e2 + e3 * e3;
    #pragma unroll
    for (int o = 16; o; o >>= 1) {
        c2  += __shfl_down_sync(0xFFFFFFFFu, c2, o);
        ec2 += __shfl_down_sync(0xFFFFFFFFu, ec2, o);
    }
    if (lane == 0) {
        g_c2[row] = c2;
        atomicMax(&g_c2max_bits[row >> 13], __float_as_int(c2));
        atomicMax(&g_ec2max_bits[row >> 13], __float_as_int(ec2));
    }
}

// split_x: f16 quantize queries + x2 + exact error norms. grid (n,b,tc)=512.
__global__ void split_x_kernel(const float* __restrict__ x) {
    __shared__ float xs[128 * 33];
    int bi = blockIdx.x;
    int n  = bi >> 8;
    int b  = (bi >> 5) & 7;
    int tc = bi & 31;
    int tid = threadIdx.x;
    {
        int tt = tid & 31, dg = tid >> 5;
        const float* xp = x + ((size_t)b * CCH + (size_t)n * DDIM) * TLEN
                          + tc * 32 + tt;
        #pragma unroll
        for (int j = 0; j < 16; ++j) {
            int d = dg * 16 + j;
            xs[d * 33 + tt] = xp[(size_t)d * TLEN];
        }
    }
    __syncthreads();
    int tcol = tid >> 3;
    int sub  = tid & 7;
    int bt   = b * TLEN + tc * 32 + tcol;
    float x2 = 0.f, ex2 = 0.f, xh2 = 0.f;
    #pragma unroll
    for (int w = 0; w < 8; ++w) {
        float a  = xs[(sub * 16 + 2 * w) * 33 + tcol];
        float bb = xs[(sub * 16 + 2 * w + 1) * 33 + tcol];
        __half ha = __float2half_rn(a), hb = __float2half_rn(bb);
        float fa = __half2float(ha), fb = __half2float(hb);
        float ea = a - fa, eb = bb - fb;
        x2  += a * a + bb * bb;
        ex2 += ea * ea + eb * eb;
        xh2 += fa * fa + fb * fb;
        g_Ahat[(size_t)(n * BT + bt) * 64 + sub * 8 + w] = pack_h2(ha, hb);
    }
    #pragma unroll
    for (int o = 4; o; o >>= 1) {
        x2  += __shfl_xor_sync(0xFFFFFFFFu, x2, o);
        ex2 += __shfl_xor_sync(0xFFFFFFFFu, ex2, o);
        xh2 += __shfl_xor_sync(0xFFFFFFFFu, xh2, o);
    }
    if (sub == 0) {
        int q = n * BT + bt;
        g_x2[q] = x2; g_ex2[q] = ex2; g_xh2[q] = xh2;
    }
}

// ---------------------------------------------------------------------------
// vq_mma (f16, K=128): one CTA per (cb n, 128-query tile). 512 thr, 16 warps.
// A resident; B 64cw tiles double-buffered; c2 staged in smem; prefetch issued
// BEFORE epilogue so the async load overlaps it. Per-thread TOP-5 per q-row.
// ---------------------------------------------------------------------------
#define ASTRIDE 272
#define BSTRIDE 272
#define SM_A    0
#define SM_B0   34816
#define SM_B1   52224
#define SM_C2S  69632          // 8192 floats
#define SM_MV   102400         // 128q x 40 floats
#define SM_MK   122880         // 128q x 40 ints
#define SM_TOT  143360

__global__ void __launch_bounds__(512, 1)
vq_mma_kernel() {
    extern __shared__ char smraw[];
    const uint32_t sb = smem_u32(smraw);
    const int tid  = threadIdx.x;
    const int wid  = tid >> 5;
    const int lane = tid & 31;
    const int gq   = lane >> 2;
    const int tq   = lane & 3;
    const int mw   = wid >> 1;          // 0-7 (16q each)
    const int nw   = wid & 1;           // 0-1 (32cw each)
    const int n    = blockIdx.x >> 6;
    const int qbase = (blockIdx.x & 63) * 128;

    const char* bsrc = (const char*)g_Bhat + (size_t)n * KCB * 256;

    // prologue: group0 = A + Btile0 ; group1 = Btile1 ; c2 -> smem (sync ld)
    {
        const char* asrc = (const char*)g_Ahat + (size_t)(n * BT + qbase) * 256;
        #pragma unroll
        for (int it = 0; it < 4; ++it) {
            int c   = it * 512 + tid;
            int row = c >> 4, col = c & 15;
            cp_async16(sb + SM_A + row * ASTRIDE + col * 16,
                       asrc + (size_t)row * 256 + col * 16);
        }
        #pragma unroll
        for (int it = 0; it < 2; ++it) {
            int c   = it * 512 + tid;
            int row = c >> 4, col = c & 15;
            cp_async16(sb + SM_B0 + row * BSTRIDE + col * 16,
                       bsrc + (size_t)row * 256 + col * 16);
        }
        CP_COMMIT();
        #pragma unroll
        for (int it = 0; it < 2; ++it) {
            int c   = it * 512 + tid;
            int row = c >> 4, col = c & 15;
            cp_async16(sb + SM_B1 + row * BSTRIDE + col * 16,
                       bsrc + (size_t)(64 + row) * 256 + col * 16);
        }
        CP_COMMIT();
        // c2 table (32 KB) into smem
        float4* dst = (float4*)(smraw + SM_C2S);
        const float4* src = (const float4*)(g_c2 + n * KCB);
        #pragma unroll
        for (int j = 0; j < 4; ++j) dst[j * 512 + tid] = src[j * 512 + tid];
    }
    CP_WAIT1();
    __syncthreads();

    const float* sc2 = (const float*)(smraw + SM_C2S);
    const uint32_t lmo = (uint32_t)(lane >> 4) * 16;
    const uint32_t aAddr = sb + SM_A +
        (uint32_t)(mw * 16 + (lane & 15)) * ASTRIDE + lmo;
    const uint32_t bAddrP[2] = {
        sb + SM_B0 + (uint32_t)(nw * 32 + (lane & 15)) * BSTRIDE + lmo,
        sb + SM_B1 + (uint32_t)(nw * 32 + (lane & 15)) * BSTRIDE + lmo };

    // per-thread top-5 per q-row (hot path: single compare vs v[r][4])
    float v[2][5];
    int   kk[2][5];
    #pragma unroll
    for (int r = 0; r < 2; ++r)
        #pragma unroll
        for (int j = 0; j < 5; ++j) { v[r][j] = 3.4e38f; kk[r][j] = 0; }

    for (int iter = 0; iter < 128; ++iter) {
        float acc[4][4];
        #pragma unroll
        for (int nt = 0; nt < 4; ++nt)
            #pragma unroll
            for (int j = 0; j < 4; ++j) acc[nt][j] = 0.f;

        const uint32_t bA = bAddrP[iter & 1];
        #pragma unroll
        for (int ks = 0; ks < 8; ++ks) {
            uint32_t a0, a1, a2, a3;
            uint32_t b0x, b0y, b1x, b1y, b0z, b0w, b1z, b1w;
            ldsm4(a0, a1, a2, a3, aAddr + ks * 32);
            ldsm4(b0x, b0y, b1x, b1y, bA + ks * 32);
            ldsm4(b0z, b0w, b1z, b1w, bA + 16 * BSTRIDE + ks * 32);
            mma_f16(acc[0], a0, a1, a2, a3, b0x, b1x);
            mma_f16(acc[1], a0, a1, a2, a3, b0y, b1y);
            mma_f16(acc[2], a0, a1, a2, a3, b0z, b1z);
            mma_f16(acc[3], a0, a1, a2, a3, b0w, b1w);
        }

        // all warps done reading buf[iter&1]; start overwriting it NOW so the
        // async load overlaps the epilogue below
        __syncthreads();
        const bool pf = (iter + 2 < 128);
        if (pf) {
            const char* src = bsrc + (size_t)(iter + 2) * 64 * 256;
            uint32_t dstb = sb + ((iter & 1) ? SM_B1 : SM_B0);
            #pragma unroll
            for (int it = 0; it < 2; ++it) {
                int c   = it * 512 + tid;
                int row = c >> 4, col = c & 15;
                cp_async16(dstb + row * BSTRIDE + col * 16,
                           src + (size_t)row * 256 + col * 16);
            }
            CP_COMMIT();
        }

        // epilogue: s = c2[k] - 2*xc (c2 from smem), per-row top-5
        const int kbw = iter * 64 + nw * 32;
        #pragma unroll
        for (int nt = 0; nt < 4; ++nt) {
            const int kg = kbw + nt * 8 + tq * 2;
            const float2 c2p = *reinterpret_cast<const float2*>(sc2 + kg);
            #pragma unroll
            for (int r = 0; r < 2; ++r) {
                #pragma unroll
                for (int h = 0; h < 2; ++h) {
                    float s  = fmaf(acc[nt][r * 2 + h], -2.0f,
                                    h ? c2p.y : c2p.x);
                    int   ki = kg + h;
                    if (s < v[r][4]) {
                        int j = 4;
                        #pragma unroll
                        for (int p = 3; p >= 0; --p) {
                            if (s < v[r][p]) {
                                v[r][p + 1] = v[r][p];
                                kk[r][p + 1] = kk[r][p];
                                j = p;
                            }
                        }
                        v[r][j] = s; kk[r][j] = ki;
                    }
                }
            }
        }

        if (pf) CP_WAIT1(); else CP_WAIT0();
        __syncthreads();
    }

    // write per-thread top-5 lists (8 lists x 5 per query)
    float* MV = (float*)(smraw + SM_MV);
    int*   MK = (int*)(smraw + SM_MK);
    #pragma unroll
    for (int r = 0; r < 2; ++r) {
        const int ql = mw * 16 + r * 8 + gq;
        const int s0 = ql * 40 + (nw * 4 + tq) * 5;
        #pragma unroll
        for (int j = 0; j < 5; ++j) {
            MV[s0 + j] = v[r][j];
            MK[s0 + j] = kk[r][j];
        }
    }
    __syncthreads();

    // merge + computed rigorous window + candidate emission (thread = query)
    if (tid < 128) {
        const int q = n * BT + qbase + tid;
        float b1 = 3.4e38f;
        int   i1 = 1 << 30;
        #pragma unroll 4
        for (int j = 0; j < 40; ++j) {
            float vv = MV[tid * 40 + j];
            int   kv = MK[tid * 40 + j];
            if (vv < b1 || (vv == b1 && kv < i1)) { b1 = vv; i1 = kv; }
        }
        float minv5 = 3.4e38f;
        #pragma unroll
        for (int l = 0; l < 8; ++l)
            minv5 = fminf(minv5, MV[tid * 40 + l * 5 + 4]);
        // win = 2*eps_q; eps_q = 2*(||ex||*maxc + ||xh||*maxec) + accum slack
        float cmax  = sqrtf(__int_as_float(g_c2max_bits[n]));
        float ecmax = sqrtf(__int_as_float(g_ec2max_bits[n]));
        float win = 4.0f * (sqrtf(g_ex2[q]) * cmax + sqrtf(g_xh2[q]) * ecmax)
                    + 2e-3f;

        int cnt;
        if (minv5 - b1 <= win) {
            cnt = -1;
        } else {
            cnt = 0;
            float thr = b1 + win;
            #pragma unroll 4
            for (int j = 0; j < 40; ++j) {
                float vv = MV[tid * 40 + j];
                if (vv <= thr) {
                    if (cnt < NCAND) g_candk[q * NCAND + cnt] = MK[tid * 40 + j];
                    ++cnt;
                }
            }
            if (cnt > NCAND) cnt = -1;
        }
        g_candn[q] = cnt;
    }
}

// ---------------------------------------------------------------------------
// exact JAX-order d2 (same arithmetic as all passing rounds)
// ---------------------------------------------------------------------------
__device__ __forceinline__ float exact_d2(const float* __restrict__ x,
                                          const float* __restrict__ cb,
                                          int n, int b, int t, int bt, int k) {
    const float* xp = x + ((size_t)b * CCH + (size_t)n * DDIM) * TLEN + t;
    const float* cp = cb + ((size_t)n * KCB + (size_t)k) * DDIM;
    float xc = 0.f;
    #pragma unroll 8
    for (int d = 0; d < DDIM; ++d) xc = fmaf(xp[(size_t)d * TLEN], cp[d], xc);
    return __fadd_rn(__fsub_rn(g_x2[n * BT + bt], __fmul_rn(2.0f, xc)),
                     g_c2[n * KCB + k]);
}

// ---------------------------------------------------------------------------
// finalize: exact rescore of the candidate set; flag fallbacks
// ---------------------------------------------------------------------------
__global__ void finalize_kernel(const float* __restrict__ x,
                                const float* __restrict__ cb,
                                float* __restrict__ out) {
    int q = blockIdx.x * 256 + threadIdx.x;
    int n = q >> 13, bt = q & 8191, b = bt >> 10, t = bt & 1023;
    int cnt = g_candn[q];
    if (cnt < 0) {
        int pos = atomicAdd(&g_nflag, 1);
        g_flagq[pos] = q;
        return;
    }
    int kf;
    if (cnt == 1) {
        kf = g_candk[q * NCAND];
    } else {
        float bd = 3.4e38f;
        kf = 1 << 30;
        for (int i = 0; i < cnt; ++i) {
            int   k = g_candk[q * NCAND + i];
            float d = exact_d2(x, cb, n, b, t, bt, k);
            if (d < bd || (d == bd && k < kf)) { bd = d; kf = k; }
        }
    }
    g_idx[q] = kf;
    out[NQ + ((size_t)b * 2 + n) * TLEN + t] = (float)kf;
}

// ---------------------------------------------------------------------------
// fallback: PARALLEL exact full scan, one CTA per flagged query (strided).
// x row cached in smem; each thread scans 32 k's with contiguous cb reads;
// arithmetic identical to exact_d2 (sequential-d fmaf chain).
// ---------------------------------------------------------------------------
__global__ void fallback_kernel(const float* __restrict__ x,
                                const float* __restrict__ cb,
                                float* __restrict__ out) {
    __shared__ float xq[128];
    __shared__ float sv[256];
    __shared__ int   sk[256];
    int nf = g_nflag;
    for (int i = blockIdx.x; i < nf; i += 256) {
        int q = g_flagq[i];
        int n = q >> 13, bt = q & 8191, b = bt >> 10, t = bt & 1023;
        if (threadIdx.x < 128)
            xq[threadIdx.x] = x[((size_t)b * CCH + (size_t)n * DDIM
                                 + threadIdx.x) * TLEN + t];
        __syncthreads();
        float x2v = g_x2[q];
        float bv = 3.4e38f;
        int   bk = 1 << 30;
        for (int j = 0; j < 32; ++j) {
            int k = j * 256 + threadIdx.x;
            const float* cp = cb + ((size_t)n * KCB + (size_t)k) * DDIM;
            float xc = 0.f;
            #pragma unroll 8
            for (int d = 0; d < DDIM; ++d) xc = fmaf(xq[d], cp[d], xc);
            float d2 = __fadd_rn(__fsub_rn(x2v, __fmul_rn(2.0f, xc)),
                                 g_c2[n * KCB + k]);
            if (d2 < bv || (d2 == bv && k < bk)) { bv = d2; bk = k; }
        }
        sv[threadIdx.x] = bv;
        sk[threadIdx.x] = bk;
        __syncthreads();
        for (int o = 128; o; o >>= 1) {
            if (threadIdx.x < o) {
                float ov = sv[threadIdx.x + o];
                int   ok = sk[threadIdx.x + o];
                if (ov < sv[threadIdx.x] ||
                    (ov == sv[threadIdx.x] && ok < sk[threadIdx.x])) {
                    sv[threadIdx.x] = ov; sk[threadIdx.x] = ok;
                }
            }
            __syncthreads();
        }
        if (threadIdx.x == 0) {
            g_idx[q] = sk[0];
            out[NQ + ((size_t)b * 2 + n) * TLEN + t] = (float)sk[0];
        }
        __syncthreads();
    }
}

// ---------------------------------------------------------------------------
// gather: coalesced quantized-output writes + commit-loss SSE.
// ---------------------------------------------------------------------------
__global__ void gather_kernel(const float* __restrict__ x,
                              const float* __restrict__ cb,
                              float* __restrict__ out) {
    __shared__ float qs[128 * 33];
    __shared__ int   kq[32];
    __shared__ float red[8];
    int bi = blockIdx.x;
    int n  = bi >> 8;
    int b  = (bi >> 5) & 7;
    int tc = bi & 31;
    int tid = threadIdx.x;
    if (tid < 32) kq[tid] = g_idx[n * BT + b * TLEN + tc * 32 + tid];
    __syncthreads();
    #pragma unroll
    for (int j = 0; j < 16; ++j) {
        int idx = j * 256 + tid;
        int cw  = idx >> 7;
        int d   = idx & 127;
        qs[d * 33 + cw] = cb[((size_t)n * KCB + kq[cw]) * DDIM + d];
    }
    __syncthreads();
    float acc = 0.f;
    #pragma unroll
    for (int j = 0; j < 16; ++j) {
        int idx = j * 256 + tid;
        int d   = idx >> 5;
        int tt  = idx & 31;
        float w = qs[d * 33 + tt];
        size_t addr = ((size_t)b * CCH + (size_t)n * DDIM + d) * TLEN
                      + tc * 32 + tt;
        out[addr] = w;
        float df = x[addr] - w;
        acc += df * df;
    }
    #pragma unroll
    for (int o = 16; o; o >>= 1) acc += __shfl_down_sync(0xFFFFFFFFu, acc, o);
    if ((tid & 31) == 0) red[tid >> 5] = acc;
    __syncthreads();
    if (tid == 0) {
        float tot = 0.f;
        #pragma unroll
        for (int j = 0; j < 8; ++j) tot += red[j];
        atomicAdd(&g_sse, (double)tot);
    }
}

__global__ void fin_kernel(float* __restrict__ out) {
    out[NQ + NIDX] = (float)(0.25 * g_sse / (double)((long long)BT * DDIM));
}

// ---------------------------------------------------------------------------
extern "C" void kernel_launch(void* const* d_in, const int* in_sizes, int n_in,
                              void* d_out, int out_size) {
    const float* x  = (const float*)d_in[0];
    const float* cb = (const float*)d_in[1];
    float* out = (float*)d_out;

    cudaFuncSetAttribute(vq_mma_kernel,
                         cudaFuncAttributeMaxDynamicSharedMemorySize, SM_TOT);

    init_kernel<<<1, 32>>>();
    splitcb_kernel<<<2048, 256>>>(cb);
    split_x_kernel<<<512, 256>>>(x);
    vq_mma_kernel<<<128, 512, SM_TOT>>>();
    finalize_kernel<<<64, 256>>>(x, cb, out);
    fallback_kernel<<<256, 256>>>(x, cb, out);
    gather_kernel<<<512, 256>>>(x, cb, out);
    fin_kernel<<<1, 1>>>(out);
}

// round 13
// speedup vs baseline: 11.0212x; 2.0110x over previous
#include <cuda_runtime.h>
#include <cuda_fp16.h>
#include <cstdint>

// Problem constants
#define BT    8192
#define KCB   8192
#define DDIM  128
#define TLEN  1024
#define CCH   256
#define NQ    2097152
#define NIDX  16384
#define NCAND 16

// ---------------------------------------------------------------------------
// Scratch (device globals; no allocation allowed)
// ---------------------------------------------------------------------------
__device__ __align__(16) unsigned g_Ahat[16384 * 64];  // f16x2 xh row (256B each)
__device__ __align__(16) unsigned g_Bhat[16384 * 64];  // f16x2 ch row (256B each)
__device__ float  g_c2[2 * KCB];
__device__ float  g_x2[2 * BT];
__device__ float  g_ex2[2 * BT];     // ||x - xh||^2  (exact)
__device__ float  g_xh2[2 * BT];     // ||xh||^2      (exact)
__device__ int    g_c2max_bits[2];   // max_k ||c_k||^2   (float bits)
__device__ int    g_ec2max_bits[2];  // max_k ||c-ch||^2  (float bits)
__device__ int    g_candk[2 * BT * NCAND];
__device__ int    g_candn[2 * BT];   // count, or -1 => fallback
__device__ int    g_idx[2 * BT];
__device__ int    g_flagq[2 * BT];
__device__ int    g_nflag;
__device__ double g_sse;

// ---------------------------------------------------------------------------
// PTX helpers (compute_103-legal only: ldmatrix / mma.sync / cp.async)
// ---------------------------------------------------------------------------
__device__ __forceinline__ uint32_t smem_u32(const void* p) {
    uint32_t a;
    asm("{ .reg .u64 t; cvta.to.shared.u64 t, %1; cvt.u32.u64 %0, t; }"
        : "=r"(a) : "l"(p));
    return a;
}
__device__ __forceinline__ void ldsm4(uint32_t& r0, uint32_t& r1,
                                      uint32_t& r2, uint32_t& r3, uint32_t a) {
    asm volatile("ldmatrix.sync.aligned.m8n8.x4.shared.b16 {%0,%1,%2,%3}, [%4];"
                 : "=r"(r0), "=r"(r1), "=r"(r2), "=r"(r3) : "r"(a));
}
__device__ __forceinline__ void mma_f16(float* d, uint32_t a0, uint32_t a1,
                                        uint32_t a2, uint32_t a3,
                                        uint32_t b0, uint32_t b1) {
    asm volatile(
        "mma.sync.aligned.m16n8k16.row.col.f32.f16.f16.f32 "
        "{%0,%1,%2,%3}, {%4,%5,%6,%7}, {%8,%9}, {%0,%1,%2,%3};"
        : "+f"(d[0]), "+f"(d[1]), "+f"(d[2]), "+f"(d[3])
        : "r"(a0), "r"(a1), "r"(a2), "r"(a3), "r"(b0), "r"(b1));
}
__device__ __forceinline__ void cp_async16(uint32_t dst, const void* src) {
    asm volatile("cp.async.cg.shared.global [%0], [%1], 16;"
                 :: "r"(dst), "l"(src) : "memory");
}
#define CP_COMMIT() asm volatile("cp.async.commit_group;" ::: "memory")
#define CP_WAIT0()  asm volatile("cp.async.wait_group 0;" ::: "memory")
#define CP_WAIT1()  asm volatile("cp.async.wait_group 1;" ::: "memory")

__device__ __forceinline__ unsigned pack_h2(__half a, __half b) {
    unsigned short ua = __half_as_ushort(a), ub = __half_as_ushort(b);
    return (unsigned)ua | ((unsigned)ub << 16);
}

// ---------------------------------------------------------------------------
__global__ void init_kernel() {
    if (blockIdx.x == 0 && threadIdx.x == 0) {
        g_sse = 0.0; g_nflag = 0;
        g_c2max_bits[0] = 0; g_c2max_bits[1] = 0;
        g_ec2max_bits[0] = 0; g_ec2max_bits[1] = 0;
    }
}

// splitcb: one warp per codeword row -> Bhat(f16 ch), c2, max c2, max ||ec||^2
__global__ void splitcb_kernel(const float* __restrict__ cb) {
    int row  = blockIdx.x * 8 + (threadIdx.x >> 5);
    int lane = threadIdx.x & 31;
    const float4 v = *reinterpret_cast<const float4*>(
        cb + (size_t)row * DDIM + lane * 4);
    __half h0 = __float2half_rn(v.x), h1 = __float2half_rn(v.y);
    __half h2 = __float2half_rn(v.z), h3 = __float2half_rn(v.w);
    g_Bhat[(size_t)row * 64 + 2 * lane]     = pack_h2(h0, h1);
    g_Bhat[(size_t)row * 64 + 2 * lane + 1] = pack_h2(h2, h3);
    float e0 = v.x - __half2float(h0), e1 = v.y - __half2float(h1);
    float e2 = v.z - __half2float(h2), e3 = v.w - __half2float(h3);
    float c2  = v.x * v.x + v.y * v.y + v.z * v.z + v.w * v.w;
    float ec2 = e0 * e0 + e1 * e1 + e2 * e2 + e3 * e3;
    #pragma unroll
    for (int o = 16; o; o >>= 1) {
        c2  += __shfl_down_sync(0xFFFFFFFFu, c2, o);
        ec2 += __shfl_down_sync(0xFFFFFFFFu, ec2, o);
    }
    if (lane == 0) {
        g_c2[row] = c2;
        atomicMax(&g_c2max_bits[row >> 13], __float_as_int(c2));
        atomicMax(&g_ec2max_bits[row >> 13], __float_as_int(ec2));
    }
}

// split_x: f16 quantize queries + x2 + exact error norms. grid (n,b,tc)=512.
__global__ void split_x_kernel(const float* __restrict__ x) {
    __shared__ float xs[128 * 33];
    int bi = blockIdx.x;
    int n  = bi >> 8;
    int b  = (bi >> 5) & 7;
    int tc = bi & 31;
    int tid = threadIdx.x;
    {
        int tt = tid & 31, dg = tid >> 5;
        const float* xp = x + ((size_t)b * CCH + (size_t)n * DDIM) * TLEN
                          + tc * 32 + tt;
        #pragma unroll
        for (int j = 0; j < 16; ++j) {
            int d = dg * 16 + j;
            xs[d * 33 + tt] = xp[(size_t)d * TLEN];
        }
    }
    __syncthreads();
    int tcol = tid >> 3;
    int sub  = tid & 7;
    int bt   = b * TLEN + tc * 32 + tcol;
    float x2 = 0.f, ex2 = 0.f, xh2 = 0.f;
    #pragma unroll
    for (int w = 0; w < 8; ++w) {
        float a  = xs[(sub * 16 + 2 * w) * 33 + tcol];
        float bb = xs[(sub * 16 + 2 * w + 1) * 33 + tcol];
        __half ha = __float2half_rn(a), hb = __float2half_rn(bb);
        float fa = __half2float(ha), fb = __half2float(hb);
        float ea = a - fa, eb = bb - fb;
        x2  += a * a + bb * bb;
        ex2 += ea * ea + eb * eb;
        xh2 += fa * fa + fb * fb;
        g_Ahat[(size_t)(n * BT + bt) * 64 + sub * 8 + w] = pack_h2(ha, hb);
    }
    #pragma unroll
    for (int o = 4; o; o >>= 1) {
        x2  += __shfl_xor_sync(0xFFFFFFFFu, x2, o);
        ex2 += __shfl_xor_sync(0xFFFFFFFFu, ex2, o);
        xh2 += __shfl_xor_sync(0xFFFFFFFFu, xh2, o);
    }
    if (sub == 0) {
        int q = n * BT + bt;
        g_x2[q] = x2; g_ex2[q] = ex2; g_xh2[q] = xh2;
    }
}

// ---------------------------------------------------------------------------
// vq_mma (f16, K=128): one CTA per (cb n, 128-query tile). 512 thr, 16 warps.
// A fragments hoisted to REGISTERS (loop-invariant); B 64cw tiles double-
// buffered via cp.async. Warp tile 16q x 32cw. Per-thread TOP-6 per q-row in
// EXPLICIT SCALARS (no arrays -> no local-mem spills).
// ---------------------------------------------------------------------------
#define ASTRIDE 272
#define BSTRIDE 272
#define SM_A    0
#define SM_B0   34816
#define SM_B1   52224
#define SM_MV   69632          // 128q x 48 floats
#define SM_MK   94208          // 128q x 48 ints
#define SM_TOT  118784

// top-6 insert, explicit scalars; common path = 1 compare
#define TOP6_INSERT(s, ki, V1, V2, V3, V4, V5, V6, K1, K2, K3, K4, K5)       \
    if ((s) < V6) {                                                          \
        if ((s) < V5) {                                                      \
            V6 = V5;                                                         \
            if ((s) < V4) {                                                  \
                V5 = V4; K5 = K4;                                            \
                if ((s) < V3) {                                              \
                    V4 = V3; K4 = K3;                                        \
                    if ((s) < V2) {                                          \
                        V3 = V2; K3 = K2;                                    \
                        if ((s) < V1) { V2 = V1; K2 = K1;                    \
                                        V1 = (s); K1 = (ki); }               \
                        else          { V2 = (s); K2 = (ki); }               \
                    } else { V3 = (s); K3 = (ki); }                          \
                } else { V4 = (s); K4 = (ki); }                              \
            } else { V5 = (s); K5 = (ki); }                                  \
        } else V6 = (s);                                                     \
    }

__global__ void __launch_bounds__(512, 1)
vq_mma_kernel() {
    extern __shared__ char smraw[];
    const uint32_t sb = smem_u32(smraw);
    const int tid  = threadIdx.x;
    const int wid  = tid >> 5;
    const int lane = tid & 31;
    const int gq   = lane >> 2;
    const int tq   = lane & 3;
    const int mw   = wid >> 1;          // 0-7 (16q each)
    const int nw   = wid & 1;           // 0-1 (32cw each)
    const int n    = blockIdx.x >> 6;
    const int qbase = (blockIdx.x & 63) * 128;

    const char* bsrc = (const char*)g_Bhat + (size_t)n * KCB * 256;

    // prologue: group0 = A + Btile0 ; group1 = Btile1
    {
        const char* asrc = (const char*)g_Ahat + (size_t)(n * BT + qbase) * 256;
        #pragma unroll
        for (int it = 0; it < 4; ++it) {
            int c   = it * 512 + tid;
            int row = c >> 4, col = c & 15;
            cp_async16(sb + SM_A + row * ASTRIDE + col * 16,
                       asrc + (size_t)row * 256 + col * 16);
        }
        #pragma unroll
        for (int it = 0; it < 2; ++it) {
            int c   = it * 512 + tid;
            int row = c >> 4, col = c & 15;
            cp_async16(sb + SM_B0 + row * BSTRIDE + col * 16,
                       bsrc + (size_t)row * 256 + col * 16);
        }
        CP_COMMIT();
        #pragma unroll
        for (int it = 0; it < 2; ++it) {
            int c   = it * 512 + tid;
            int row = c >> 4, col = c & 15;
            cp_async16(sb + SM_B1 + row * BSTRIDE + col * 16,
                       bsrc + (size_t)(64 + row) * 256 + col * 16);
        }
        CP_COMMIT();
    }
    CP_WAIT1();
    __syncthreads();

    const uint32_t lmo = (uint32_t)(lane >> 4) * 16;
    const uint32_t aAddr = sb + SM_A +
        (uint32_t)(mw * 16 + (lane & 15)) * ASTRIDE + lmo;
    const uint32_t bAddrP[2] = {
        sb + SM_B0 + (uint32_t)(nw * 32 + (lane & 15)) * BSTRIDE + lmo,
        sb + SM_B1 + (uint32_t)(nw * 32 + (lane & 15)) * BSTRIDE + lmo };

    // ---- hoist A fragments into registers (loop-invariant) ----
    uint32_t aF[8][4];
    #pragma unroll
    for (int ks = 0; ks < 8; ++ks)
        ldsm4(aF[ks][0], aF[ks][1], aF[ks][2], aF[ks][3], aAddr + ks * 32);

    // per-row top-6 scalars
    float v1a, v2a, v3a, v4a, v5a, v6a, v1b, v2b, v3b, v4b, v5b, v6b;
    int   k1a, k2a, k3a, k4a, k5a, k1b, k2b, k3b, k4b, k5b;
    v1a = v2a = v3a = v4a = v5a = v6a = 3.4e38f;
    v1b = v2b = v3b = v4b = v5b = v6b = 3.4e38f;
    k1a = k2a = k3a = k4a = k5a = 0;
    k1b = k2b = k3b = k4b = k5b = 0;

    for (int iter = 0; iter < 128; ++iter) {
        float acc[4][4];
        #pragma unroll
        for (int nt = 0; nt < 4; ++nt)
            #pragma unroll
            for (int j = 0; j < 4; ++j) acc[nt][j] = 0.f;

        const uint32_t bA = bAddrP[iter & 1];
        #pragma unroll
        for (int ks = 0; ks < 8; ++ks) {
            uint32_t b0x, b0y, b1x, b1y, b0z, b0w, b1z, b1w;
            ldsm4(b0x, b0y, b1x, b1y, bA + ks * 32);
            ldsm4(b0z, b0w, b1z, b1w, bA + 16 * BSTRIDE + ks * 32);
            mma_f16(acc[0], aF[ks][0], aF[ks][1], aF[ks][2], aF[ks][3], b0x, b1x);
            mma_f16(acc[1], aF[ks][0], aF[ks][1], aF[ks][2], aF[ks][3], b0y, b1y);
            mma_f16(acc[2], aF[ks][0], aF[ks][1], aF[ks][2], aF[ks][3], b0z, b1z);
            mma_f16(acc[3], aF[ks][0], aF[ks][1], aF[ks][2], aF[ks][3], b0w, b1w);
        }

        // epilogue: s = c2[k] - 2*xc, per-row top-6 (scalar regs)
        const int kbw = iter * 64 + nw * 32;
        #pragma unroll
        for (int nt = 0; nt < 4; ++nt) {
            const int kg = kbw + nt * 8 + tq * 2;
            const float2 c2p = __ldg(reinterpret_cast<const float2*>(
                g_c2 + n * KCB + kg));
            {
                float s0 = fmaf(acc[nt][0], -2.0f, c2p.x);
                TOP6_INSERT(s0, kg, v1a, v2a, v3a, v4a, v5a, v6a,
                            k1a, k2a, k3a, k4a, k5a);
                float s1 = fmaf(acc[nt][1], -2.0f, c2p.y);
                TOP6_INSERT(s1, kg + 1, v1a, v2a, v3a, v4a, v5a, v6a,
                            k1a, k2a, k3a, k4a, k5a);
            }
            {
                float s0 = fmaf(acc[nt][2], -2.0f, c2p.x);
                TOP6_INSERT(s0, kg, v1b, v2b, v3b, v4b, v5b, v6b,
                            k1b, k2b, k3b, k4b, k5b);
                float s1 = fmaf(acc[nt][3], -2.0f, c2p.y);
                TOP6_INSERT(s1, kg + 1, v1b, v2b, v3b, v4b, v5b, v6b,
                            k1b, k2b, k3b, k4b, k5b);
            }
        }

        __syncthreads();
        if (iter + 2 < 128) {
            const char* src = bsrc + (size_t)(iter + 2) * 64 * 256;
            uint32_t dstb = sb + ((iter & 1) ? SM_B1 : SM_B0);
            #pragma unroll
            for (int it = 0; it < 2; ++it) {
                int c   = it * 512 + tid;
                int row = c >> 4, col = c & 15;
                cp_async16(dstb + row * BSTRIDE + col * 16,
                           src + (size_t)row * 256 + col * 16);
            }
            CP_COMMIT();
            CP_WAIT1();
        } else {
            CP_WAIT0();
        }
        __syncthreads();
    }

    // write per-thread top-6 lists (8 lists x 6 per query); slot-6 k unused
    float* MV = (float*)(smraw + SM_MV);
    int*   MK = (int*)(smraw + SM_MK);
    {
        const int qlA = mw * 16 + gq;
        const int sA  = qlA * 48 + (nw * 4 + tq) * 6;
        MV[sA + 0] = v1a; MK[sA + 0] = k1a;
        MV[sA + 1] = v2a; MK[sA + 1] = k2a;
        MV[sA + 2] = v3a; MK[sA + 2] = k3a;
        MV[sA + 3] = v4a; MK[sA + 3] = k4a;
        MV[sA + 4] = v5a; MK[sA + 4] = k5a;
        MV[sA + 5] = v6a; MK[sA + 5] = 0;
        const int qlB = mw * 16 + 8 + gq;
        const int sB  = qlB * 48 + (nw * 4 + tq) * 6;
        MV[sB + 0] = v1b; MK[sB + 0] = k1b;
        MV[sB + 1] = v2b; MK[sB + 1] = k2b;
        MV[sB + 2] = v3b; MK[sB + 2] = k3b;
        MV[sB + 3] = v4b; MK[sB + 3] = k4b;
        MV[sB + 4] = v5b; MK[sB + 4] = k5b;
        MV[sB + 5] = v6b; MK[sB + 5] = 0;
    }
    __syncthreads();

    // merge + computed rigorous window + candidate emission (thread = query)
    if (tid < 128) {
        const int q = n * BT + qbase + tid;
        float b1 = 3.4e38f;
        int   i1 = 1 << 30;
        #pragma unroll 4
        for (int j = 0; j < 48; ++j) {
            float vv = MV[tid * 48 + j];
            int   kv = MK[tid * 48 + j];
            if (vv < b1 || (vv == b1 && kv < i1)) { b1 = vv; i1 = kv; }
        }
        float minv6 = 3.4e38f;
        #pragma unroll
        for (int l = 0; l < 8; ++l)
            minv6 = fminf(minv6, MV[tid * 48 + l * 6 + 5]);
        // win = 2*eps_q; eps_q = 2*(||ex||*maxc + ||xh||*maxec) + accum slack
        float cmax  = sqrtf(__int_as_float(g_c2max_bits[n]));
        float ecmax = sqrtf(__int_as_float(g_ec2max_bits[n]));
        float win = 4.0f * (sqrtf(g_ex2[q]) * cmax + sqrtf(g_xh2[q]) * ecmax)
                    + 2e-3f;

        int cnt;
        if (minv6 - b1 <= win) {
            cnt = -1;
        } else {
            cnt = 0;
            float thr = b1 + win;
            #pragma unroll 4
            for (int j = 0; j < 48; ++j) {
                float vv = MV[tid * 48 + j];
                if (vv <= thr) {
                    if (cnt < NCAND) g_candk[q * NCAND + cnt] = MK[tid * 48 + j];
                    ++cnt;
                }
            }
            if (cnt > NCAND) cnt = -1;
        }
        g_candn[q] = cnt;
    }
}

// ---------------------------------------------------------------------------
// exact JAX-order d2 (same arithmetic as all passing rounds)
// ---------------------------------------------------------------------------
__device__ __forceinline__ float exact_d2(const float* __restrict__ x,
                                          const float* __restrict__ cb,
                                          int n, int b, int t, int bt, int k) {
    const float* xp = x + ((size_t)b * CCH + (size_t)n * DDIM) * TLEN + t;
    const float* cp = cb + ((size_t)n * KCB + (size_t)k) * DDIM;
    float xc = 0.f;
    #pragma unroll 8
    for (int d = 0; d < DDIM; ++d) xc = fmaf(xp[(size_t)d * TLEN], cp[d], xc);
    return __fadd_rn(__fsub_rn(g_x2[n * BT + bt], __fmul_rn(2.0f, xc)),
                     g_c2[n * KCB + k]);
}

// ---------------------------------------------------------------------------
// finalize: exact rescore of the candidate set; flag fallbacks
// ---------------------------------------------------------------------------
__global__ void finalize_kernel(const float* __restrict__ x,
                                const float* __restrict__ cb,
                                float* __restrict__ out) {
    int q = blockIdx.x * 256 + threadIdx.x;
    int n = q >> 13, bt = q & 8191, b = bt >> 10, t = bt & 1023;
    int cnt = g_candn[q];
    if (cnt < 0) {
        int pos = atomicAdd(&g_nflag, 1);
        g_flagq[pos] = q;
        return;
    }
    int kf;
    if (cnt == 1) {
        kf = g_candk[q * NCAND];
    } else {
        float bd = 3.4e38f;
        kf = 1 << 30;
        for (int i = 0; i < cnt; ++i) {
            int   k = g_candk[q * NCAND + i];
            float d = exact_d2(x, cb, n, b, t, bt, k);
            if (d < bd || (d == bd && k < kf)) { bd = d; kf = k; }
        }
    }
    g_idx[q] = kf;
    out[NQ + ((size_t)b * 2 + n) * TLEN + t] = (float)kf;
}

// ---------------------------------------------------------------------------
// fallback: PARALLEL exact full scan, one CTA per flagged query (strided).
// ---------------------------------------------------------------------------
__global__ void fallback_kernel(const float* __restrict__ x,
                                const float* __restrict__ cb,
                                float* __restrict__ out) {
    __shared__ float xq[128];
    __shared__ float sv[256];
    __shared__ int   sk[256];
    int nf = g_nflag;
    for (int i = blockIdx.x; i < nf; i += 256) {
        int q = g_flagq[i];
        int n = q >> 13, bt = q & 8191, b = bt >> 10, t = bt & 1023;
        if (threadIdx.x < 128)
            xq[threadIdx.x] = x[((size_t)b * CCH + (size_t)n * DDIM
                                 + threadIdx.x) * TLEN + t];
        __syncthreads();
        float x2v = g_x2[q];
        float bv = 3.4e38f;
        int   bk = 1 << 30;
        for (int j = 0; j < 32; ++j) {
            int k = j * 256 + threadIdx.x;
            const float* cp = cb + ((size_t)n * KCB + (size_t)k) * DDIM;
            float xc = 0.f;
            #pragma unroll 8
            for (int d = 0; d < DDIM; ++d) xc = fmaf(xq[d], cp[d], xc);
            float d2 = __fadd_rn(__fsub_rn(x2v, __fmul_rn(2.0f, xc)),
                                 g_c2[n * KCB + k]);
            if (d2 < bv || (d2 == bv && k < bk)) { bv = d2; bk = k; }
        }
        sv[threadIdx.x] = bv;
        sk[threadIdx.x] = bk;
        __syncthreads();
        for (int o = 128; o; o >>= 1) {
            if (threadIdx.x < o) {
                float ov = sv[threadIdx.x + o];
                int   ok = sk[threadIdx.x + o];
                if (ov < sv[threadIdx.x] ||
                    (ov == sv[threadIdx.x] && ok < sk[threadIdx.x])) {
                    sv[threadIdx.x] = ov; sk[threadIdx.x] = ok;
                }
            }
            __syncthreads();
        }
        if (threadIdx.x == 0) {
            g_idx[q] = sk[0];
            out[NQ + ((size_t)b * 2 + n) * TLEN + t] = (float)sk[0];
        }
        __syncthreads();
    }
}

// ---------------------------------------------------------------------------
// gather: coalesced quantized-output writes + commit-loss SSE.
// ---------------------------------------------------------------------------
__global__ void gather_kernel(const float* __restrict__ x,
                              const float* __restrict__ cb,
                              float* __restrict__ out) {
    __shared__ float qs[128 * 33];
    __shared__ int   kq[32];
    __shared__ float red[8];
    int bi = blockIdx.x;
    int n  = bi >> 8;
    int b  = (bi >> 5) & 7;
    int tc = bi & 31;
    int tid = threadIdx.x;
    if (tid < 32) kq[tid] = g_idx[n * BT + b * TLEN + tc * 32 + tid];
    __syncthreads();
    #pragma unroll
    for (int j = 0; j < 16; ++j) {
        int idx = j * 256 + tid;
        int cw  = idx >> 7;
        int d   = idx & 127;
        qs[d * 33 + cw] = cb[((size_t)n * KCB + kq[cw]) * DDIM + d];
    }
    __syncthreads();
    float acc = 0.f;
    #pragma unroll
    for (int j = 0; j < 16; ++j) {
        int idx = j * 256 + tid;
        int d   = idx >> 5;
        int tt  = idx & 31;
        float w = qs[d * 33 + tt];
        size_t addr = ((size_t)b * CCH + (size_t)n * DDIM + d) * TLEN
                      + tc * 32 + tt;
        out[addr] = w;
        float df = x[addr] - w;
        acc += df * df;
    }
    #pragma unroll
    for (int o = 16; o; o >>= 1) acc += __shfl_down_sync(0xFFFFFFFFu, acc, o);
    if ((tid & 31) == 0) red[tid >> 5] = acc;
    __syncthreads();
    if (tid == 0) {
        float tot = 0.f;
        #pragma unroll
        for (int j = 0; j < 8; ++j) tot += red[j];
        atomicAdd(&g_sse, (double)tot);
    }
}

__global__ void fin_kernel(float* __restrict__ out) {
    out[NQ + NIDX] = (float)(0.25 * g_sse / (double)((long long)BT * DDIM));
}

// ---------------------------------------------------------------------------
extern "C" void kernel_launch(void* const* d_in, const int* in_sizes, int n_in,
                              void* d_out, int out_size) {
    const float* x  = (const float*)d_in[0];
    const float* cb = (const float*)d_in[1];
    float* out = (float*)d_out;

    cudaFuncSetAttribute(vq_mma_kernel,
                         cudaFuncAttributeMaxDynamicSharedMemorySize, SM_TOT);

    init_kernel<<<1, 32>>>();
    splitcb_kernel<<<2048, 256>>>(cb);
    split_x_kernel<<<512, 256>>>(x);
    vq_mma_kernel<<<128, 512, SM_TOT>>>();
    finalize_kernel<<<64, 256>>>(x, cb, out);
    fallback_kernel<<<256, 256>>>(x, cb, out);
    gather_kernel<<<512, 256>>>(x, cb, out);
    fin_kernel<<<1, 1>>>(out);
}